// round 6
// baseline (speedup 1.0000x reference)
#include <cuda_runtime.h>
#include <math_constants.h>
#include <cstdint>

#define BB 4
#define TT 2048
#define DM 1024
#define NH 16
#define DH 64

// Scratch. "prepped" = tf32-rounded bits, k-pair interleaved within 8-groups.
__device__ float g_qkv2[(size_t)BB * TT * 3 * DM]; // q,k prepped(+rope); v raw
__device__ float g_vt  [(size_t)BB * TT * DM];     // V transposed per (b,h): [bh][d][t], prepped
__device__ float g_att [(size_t)BB * TT * DM];     // attention out, prepped for proj
__device__ float g_xT  [(size_t)BB * TT * DM];     // prepped x
__device__ float g_wq  [(size_t)3 * DM * DM];      // prepped qkv_w
__device__ float g_wp  [(size_t)DM * DM];          // prepped proj_w

// ===========================================================================
// Helpers
// ===========================================================================
__device__ __forceinline__ uint32_t f2tf32(float f) {
    uint32_t u;
    asm("cvt.rna.tf32.f32 %0, %1;" : "=r"(u) : "f"(f));
    return u;
}
__device__ __forceinline__ float rna(float f) { return __uint_as_float(f2tf32(f)); }

__device__ __forceinline__ void mma8(float* c, const uint32_t* a,
                                     uint32_t b0, uint32_t b1) {
    asm volatile(
        "mma.sync.aligned.m16n8k8.row.col.f32.tf32.tf32.f32 "
        "{%0,%1,%2,%3}, {%4,%5,%6,%7}, {%8,%9}, {%0,%1,%2,%3};"
        : "+f"(c[0]), "+f"(c[1]), "+f"(c[2]), "+f"(c[3])
        : "r"(a[0]), "r"(a[1]), "r"(a[2]), "r"(a[3]), "r"(b0), "r"(b1));
}

__device__ __forceinline__ uint32_t smem_u32(const void* p) {
    uint32_t a;
    asm("{ .reg .u64 t; cvta.to.shared.u64 t, %1; cvt.u32.u64 %0, t; }"
        : "=r"(a) : "l"(p));
    return a;
}
__device__ __forceinline__ void cpa16(uint32_t s, const void* g) {
    asm volatile("cp.async.ca.shared.global [%0], [%1], 16;" :: "r"(s), "l"(g));
}
#define CPA_COMMIT() asm volatile("cp.async.commit_group;" ::: "memory")
#define CPA_WAIT(n)  asm volatile("cp.async.wait_group %0;" :: "n"(n) : "memory")

// interleave permutation within 8-k groups: pairs (k, k+4) become adjacent
__device__ __forceinline__ int perm8(int k) {
    return (k & ~7) | (2 * (k & 3)) | ((k >> 2) & 1);
}

// ===========================================================================
// prep_plain: tf32-round + k-pair interleave, 8 consecutive elements/thread
// ===========================================================================
__global__ void prep_plain(const float* __restrict__ src, float* __restrict__ dst,
                           int n8) {
    int i = blockIdx.x * blockDim.x + threadIdx.x;
    if (i >= n8) return;
    const float4* s = (const float4*)src + (size_t)i * 2;
    float4 v0 = s[0], v1 = s[1];
    float4 o0, o1;
    o0.x = rna(v0.x); o0.y = rna(v1.x); o0.z = rna(v0.y); o0.w = rna(v1.y);
    o1.x = rna(v0.z); o1.y = rna(v1.z); o1.z = rna(v0.w); o1.w = rna(v1.w);
    float4* d = (float4*)dst + (size_t)i * 2;
    d[0] = o0; d[1] = o1;
}

// ===========================================================================
// transpose_v: per (b,h), V [t][d] -> V^T [d][t], rna + key-interleave along t.
// Blocks: (TT/128, BB*NH), 256 threads. smem 128x69.
// ===========================================================================
__global__ void transpose_v(const float* __restrict__ qkv2, float* __restrict__ vt) {
    __shared__ float ts[128 * 69];
    const int tid = threadIdx.x;
    const int bh  = blockIdx.y;
    const int b   = bh >> 4;
    const int hh  = bh & 15;
    const int t0  = blockIdx.x * 128;

    const float* src = qkv2 + (size_t)b * TT * (3 * DM) + 2 * DM + hh * 64;
    #pragma unroll
    for (int it = 0; it < 8; it++) {
        int lin = tid + it * 256;          // 0..2047 float4s
        int r = lin >> 4, c4 = lin & 15;
        float4 v = *(const float4*)(src + (size_t)(t0 + r) * (3 * DM) + c4 * 4);
        ts[r * 69 + c4 * 4 + 0] = v.x;
        ts[r * 69 + c4 * 4 + 1] = v.y;
        ts[r * 69 + c4 * 4 + 2] = v.z;
        ts[r * 69 + c4 * 4 + 3] = v.w;
    }
    __syncthreads();

    float* dst = vt + (size_t)bh * 64 * TT + t0;
    #pragma unroll
    for (int it = 0; it < 32; it++) {
        int lin = tid + it * 256;          // 0..8191
        int d = lin >> 7, c = lin & 127;
        // column c holds original key tl (inverse interleave)
        int tl = (c & ~7) | ((c & 1) << 2) | ((c >> 1) & 3);
        dst[(size_t)d * TT + c] = rna(ts[tl * 69 + d]);
    }
}

// ===========================================================================
// GEMM: C = A @ W^T + bias. A,W prepped. CTA 128x128, 4 warps, warp 64x64.
// mode 0: plain fp32 output (final). mode 1: qkv-prep output
//   (q: rope*0.125+rna+perm; k: rope+rna+perm; v: raw fp32).
// ===========================================================================
#define GSTR 40
#define GTILEW (128 * GSTR)
#define GSMEM_TOTAL (4 * GTILEW * 4)

__global__ void __launch_bounds__(128, 2)
gemm_tc(const float* __restrict__ A, const float* __restrict__ W,
        const float* __restrict__ bias, float* __restrict__ C,
        int M, int N, int K, int mode,
        const float* __restrict__ fcos, const float* __restrict__ fsin) {
    extern __shared__ float gsm[];
    const int tid  = threadIdx.x;
    const int wid  = tid >> 5;
    const int lane = tid & 31;
    const int g    = lane >> 2;
    const int tig  = lane & 3;
    const int wm   = wid & 1;
    const int wn   = wid >> 1;

    const int m0 = blockIdx.y * 128;
    const int n0 = blockIdx.x * 128;
    const uint32_t sbase = smem_u32(gsm);

    float acc[4][8][4];
    #pragma unroll
    for (int i = 0; i < 4; i++)
        #pragma unroll
        for (int j = 0; j < 8; j++)
            #pragma unroll
            for (int e = 0; e < 4; e++) acc[i][j][e] = 0.f;

    const int NK = K >> 5;

    auto load_stage = [&](int st, int k0) {
        #pragma unroll
        for (int it = 0; it < 16; it++) {
            int lin   = tid + it * 128;
            int which = lin >> 10;
            int r     = (lin & 1023) >> 3;
            int c4    = lin & 7;
            const float* src = which
                ? W + (size_t)(n0 + r) * K + k0 + c4 * 4
                : A + (size_t)(m0 + r) * K + k0 + c4 * 4;
            cpa16(sbase + (uint32_t)((st * 2 + which) * GTILEW + r * GSTR + c4 * 4) * 4,
                  src);
        }
    };

    load_stage(0, 0);
    CPA_COMMIT();

    for (int kt = 0; kt < NK; kt++) {
        if (kt + 1 < NK) {
            load_stage((kt + 1) & 1, (kt + 1) << 5);
            CPA_COMMIT();
            CPA_WAIT(1);
        } else {
            CPA_WAIT(0);
        }
        __syncthreads();

        const float* sA = gsm + (kt & 1) * 2 * GTILEW;
        const float* sB = sA + GTILEW;

        #pragma unroll
        for (int s = 0; s < 4; s++) {
            int ks = s * 8;
            uint32_t a[4][4];
            #pragma unroll
            for (int i = 0; i < 4; i++) {
                int r = wm * 64 + i * 16 + g;
                uint2 lo = *(const uint2*)&sA[r * GSTR + ks + 2 * tig];
                uint2 hi = *(const uint2*)&sA[(r + 8) * GSTR + ks + 2 * tig];
                a[i][0] = lo.x; a[i][1] = hi.x; a[i][2] = lo.y; a[i][3] = hi.y;
            }
            #pragma unroll
            for (int j = 0; j < 8; j++) {
                int n = wn * 64 + j * 8 + g;
                uint2 b = *(const uint2*)&sB[n * GSTR + ks + 2 * tig];
                #pragma unroll
                for (int i = 0; i < 4; i++) mma8(acc[i][j], a[i], b.x, b.y);
            }
        }
        __syncthreads();
    }

    #pragma unroll
    for (int i = 0; i < 4; i++) {
        int row0 = m0 + wm * 64 + i * 16 + g;
        int row1 = row0 + 8;
        #pragma unroll
        for (int j = 0; j < 8; j++) {
            int col = n0 + wn * 64 + j * 8 + 2 * tig;
            float bv0 = bias[col], bv1 = bias[col + 1];
            float v00 = acc[i][j][0] + bv0, v01 = acc[i][j][1] + bv1;
            float v10 = acc[i][j][2] + bv0, v11 = acc[i][j][3] + bv1;
            if (mode == 0) {
                *(float2*)(C + (size_t)row0 * N + col) = make_float2(v00, v01);
                *(float2*)(C + (size_t)row1 * N + col) = make_float2(v10, v11);
            } else {
                int sec = col >> 10;           // 0 q, 1 k, 2 v
                int d   = col & 63;
                if (sec < 2) {
                    float sc = (sec == 0) ? 0.125f : 1.f;
                    int t0i = row0 & (TT - 1), t1i = row1 & (TT - 1);
                    float c0 = fcos[t0i * 32 + (d >> 1)], s0 = fsin[t0i * 32 + (d >> 1)];
                    float c1 = fcos[t1i * 32 + (d >> 1)], s1 = fsin[t1i * 32 + (d >> 1)];
                    float r00 = (v00 * c0 - v01 * s0) * sc;
                    float r01 = (v00 * s0 + v01 * c0) * sc;
                    float r10 = (v10 * c1 - v11 * s1) * sc;
                    float r11 = (v10 * s1 + v11 * c1) * sc;
                    int cb = col & ~63;
                    int p0 = cb + perm8(d), p1 = cb + perm8(d + 1);
                    C[(size_t)row0 * N + p0] = rna(r00);
                    C[(size_t)row0 * N + p1] = rna(r01);
                    C[(size_t)row1 * N + p0] = rna(r10);
                    C[(size_t)row1 * N + p1] = rna(r11);
                } else {
                    *(float2*)(C + (size_t)row0 * N + col) = make_float2(v00, v01);
                    *(float2*)(C + (size_t)row1 * N + col) = make_float2(v10, v11);
                }
            }
        }
    }
}

// ===========================================================================
// Flash attention v6: 256-q blocks, 8 warps x 32 q-rows, P via shuffles,
// V consumed transposed+interleaved (LDS.64, conflict-free).
// ===========================================================================
#define AST 72
#define KVW (64 * AST)
#define QSW (256 * AST)
#define ASMEM_WORDS (QSW + 4 * KVW)
#define ASMEM_TOTAL (ASMEM_WORDS * 4)   // 147456 B

__global__ void __launch_bounds__(256, 1)
attn_tc(const float* __restrict__ qkv2, const float* __restrict__ vt,
        float* __restrict__ att_out) {
    extern __shared__ float asmf[];
    float* QS = asmf;
    float* KT = asmf + QSW;
    float* VT = asmf + QSW + 2 * KVW;
    const uint32_t sbase = smem_u32(asmf);

    const int tid  = threadIdx.x;
    const int w    = tid >> 5;
    const int lane = tid & 31;
    const int g    = lane >> 2;
    const int tig  = lane & 3;
    const int rb   = w * 32;                    // warp's local query row base

    const int b   = blockIdx.y >> 4;
    const int hh  = blockIdx.y & 15;
    const int bxx = gridDim.x - 1 - blockIdx.x; // longest blocks first
    const int q0  = bxx * 256;

    const float* qb = qkv2 + (size_t)b * TT * (3 * DM) + hh * 64;          // q section
    const float* kb = qb + DM;                                             // k section
    const float* vb = vt + (size_t)blockIdx.y * 64 * TT;                   // V^T rows d

    // --- stage Q (prepped) : 256 rows x 16 chunks ---
    #pragma unroll
    for (int it = 0; it < 16; it++) {
        int lin = tid + it * 256;               // 0..4095
        int r = lin >> 4, c4 = lin & 15;
        cpa16(sbase + (uint32_t)(r * AST + c4 * 4) * 4,
              qb + (size_t)(q0 + r) * (3 * DM) + c4 * 4);
    }
    CPA_COMMIT();

    auto stage_kv = [&](int buf, int j0) {
        #pragma unroll
        for (int it = 0; it < 8; it++) {
            int lin   = tid + it * 256;         // 0..2047
            int which = lin >> 10;              // 0 K, 1 V
            int r  = (lin & 1023) >> 4;         // 0..63
            int c4 = lin & 15;
            const float* src = which
                ? vb + (size_t)r * TT + j0 + c4 * 4
                : kb + (size_t)(j0 + r) * (3 * DM) + c4 * 4;
            cpa16(sbase + (uint32_t)(QSW + (which * 2 + buf) * KVW
                                     + r * AST + c4 * 4) * 4, src);
        }
    };

    stage_kv(0, 0);
    CPA_COMMIT();
    CPA_WAIT(1);          // Q done
    __syncthreads();

    // --- Q fragments: qa[i][s][4], i = 16-row group, s = k-group ---
    uint32_t qa[2][8][4];
    #pragma unroll
    for (int i = 0; i < 2; i++)
        #pragma unroll
        for (int s = 0; s < 8; s++) {
            int r = rb + i * 16 + g;
            uint2 lo = *(const uint2*)&QS[r * AST + s * 8 + 2 * tig];
            uint2 hi = *(const uint2*)&QS[(r + 8) * AST + s * 8 + 2 * tig];
            qa[i][s][0] = lo.x; qa[i][s][1] = hi.x;
            qa[i][s][2] = lo.y; qa[i][s][3] = hi.y;
        }

    float o[2][8][4];
    #pragma unroll
    for (int i = 0; i < 2; i++)
        #pragma unroll
        for (int j = 0; j < 8; j++)
            #pragma unroll
            for (int e = 0; e < 4; e++) o[i][j][e] = 0.f;
    float mv[2][2] = {{-CUDART_INF_F, -CUDART_INF_F}, {-CUDART_INF_F, -CUDART_INF_F}};
    float lv[2][2] = {{0.f, 0.f}, {0.f, 0.f}};

    const int ntiles = 4 * (bxx + 1);
    const int srcA = 4 * g + (tig >> 1);
    const int srcB = srcA + 2;
    const bool odd = tig & 1;

    for (int tile = 0; tile < ntiles; tile++) {
        const int j0  = tile * 64;
        const int cur = tile & 1;

        if (tile + 1 < ntiles) {
            stage_kv(cur ^ 1, j0 + 64);
            CPA_COMMIT();
            CPA_WAIT(1);
        } else {
            CPA_WAIT(0);
        }
        __syncthreads();

        const float* Kc = KT + cur * KVW;
        const float* Vc = VT + cur * KVW;
        const bool active = (j0 <= q0 + rb + 31);

        if (active) {
            // --- S = Q @ K^T ---
            float p[2][8][4];
            #pragma unroll
            for (int i = 0; i < 2; i++)
                #pragma unroll
                for (int j = 0; j < 8; j++)
                    #pragma unroll
                    for (int e = 0; e < 4; e++) p[i][j][e] = 0.f;
            #pragma unroll
            for (int s = 0; s < 8; s++) {
                int ks = s * 8;
                #pragma unroll
                for (int j = 0; j < 8; j++) {
                    uint2 bb = *(const uint2*)&Kc[(j * 8 + g) * AST + ks + 2 * tig];
                    mma8(p[0][j], qa[0][s], bb.x, bb.y);
                    mma8(p[1][j], qa[1][s], bb.x, bb.y);
                }
            }

            // --- causal mask on diagonal tiles ---
            if (j0 + 63 > q0 + rb) {
                #pragma unroll
                for (int i = 0; i < 2; i++) {
                    int row0 = q0 + rb + i * 16 + g;
                    int row1 = row0 + 8;
                    #pragma unroll
                    for (int j = 0; j < 8; j++) {
                        int col = j0 + j * 8 + 2 * tig;
                        if (col > row0)     p[i][j][0] = -CUDART_INF_F;
                        if (col + 1 > row0) p[i][j][1] = -CUDART_INF_F;
                        if (col > row1)     p[i][j][2] = -CUDART_INF_F;
                        if (col + 1 > row1) p[i][j][3] = -CUDART_INF_F;
                    }
                }
            }

            // --- online softmax (per i, per row-half) ---
            #pragma unroll
            for (int i = 0; i < 2; i++) {
                float r0 = -CUDART_INF_F, r1 = -CUDART_INF_F;
                #pragma unroll
                for (int j = 0; j < 8; j++) {
                    r0 = fmaxf(r0, fmaxf(p[i][j][0], p[i][j][1]));
                    r1 = fmaxf(r1, fmaxf(p[i][j][2], p[i][j][3]));
                }
                r0 = fmaxf(r0, __shfl_xor_sync(0xffffffffu, r0, 1));
                r0 = fmaxf(r0, __shfl_xor_sync(0xffffffffu, r0, 2));
                r1 = fmaxf(r1, __shfl_xor_sync(0xffffffffu, r1, 1));
                r1 = fmaxf(r1, __shfl_xor_sync(0xffffffffu, r1, 2));
                float nm0 = fmaxf(mv[i][0], r0);
                float nm1 = fmaxf(mv[i][1], r1);
                float sc0 = __expf(mv[i][0] - nm0);
                float sc1 = __expf(mv[i][1] - nm1);
                float ls0 = 0.f, ls1 = 0.f;
                #pragma unroll
                for (int j = 0; j < 8; j++) {
                    p[i][j][0] = __expf(p[i][j][0] - nm0);
                    p[i][j][1] = __expf(p[i][j][1] - nm0);
                    p[i][j][2] = __expf(p[i][j][2] - nm1);
                    p[i][j][3] = __expf(p[i][j][3] - nm1);
                    ls0 += p[i][j][0] + p[i][j][1];
                    ls1 += p[i][j][2] + p[i][j][3];
                }
                ls0 += __shfl_xor_sync(0xffffffffu, ls0, 1);
                ls0 += __shfl_xor_sync(0xffffffffu, ls0, 2);
                ls1 += __shfl_xor_sync(0xffffffffu, ls1, 1);
                ls1 += __shfl_xor_sync(0xffffffffu, ls1, 2);
                mv[i][0] = nm0; mv[i][1] = nm1;
                lv[i][0] = lv[i][0] * sc0 + ls0;
                lv[i][1] = lv[i][1] * sc1 + ls1;
                #pragma unroll
                for (int j = 0; j < 8; j++) {
                    o[i][j][0] *= sc0; o[i][j][1] *= sc0;
                    o[i][j][2] *= sc1; o[i][j][3] *= sc1;
                }
            }

            // --- O += P @ V : P moved to A-frag layout via shuffles ---
            #pragma unroll
            for (int s = 0; s < 8; s++) {
                uint32_t pa[2][4];
                #pragma unroll
                for (int i = 0; i < 2; i++) {
                    float x0 = __shfl_sync(0xffffffffu, p[i][s][0], srcA);
                    float x1 = __shfl_sync(0xffffffffu, p[i][s][1], srcA);
                    float x2 = __shfl_sync(0xffffffffu, p[i][s][2], srcA);
                    float x3 = __shfl_sync(0xffffffffu, p[i][s][3], srcA);
                    float y0 = __shfl_sync(0xffffffffu, p[i][s][0], srcB);
                    float y1 = __shfl_sync(0xffffffffu, p[i][s][1], srcB);
                    float y2 = __shfl_sync(0xffffffffu, p[i][s][2], srcB);
                    float y3 = __shfl_sync(0xffffffffu, p[i][s][3], srcB);
                    pa[i][0] = __float_as_uint(odd ? x1 : x0);
                    pa[i][1] = __float_as_uint(odd ? x3 : x2);
                    pa[i][2] = __float_as_uint(odd ? y1 : y0);
                    pa[i][3] = __float_as_uint(odd ? y3 : y2);
                }
                int ks = s * 8;
                #pragma unroll
                for (int dj = 0; dj < 8; dj++) {
                    uint2 vv = *(const uint2*)&Vc[(dj * 8 + g) * AST + ks + 2 * tig];
                    mma8(o[0][dj], pa[0], vv.x, vv.y);
                    mma8(o[1][dj], pa[1], vv.x, vv.y);
                }
            }
        }
        __syncthreads();
    }

    // --- normalize + store prepped (rna + perm8) for proj GEMM ---
    #pragma unroll
    for (int i = 0; i < 2; i++) {
        float inv0 = 1.f / lv[i][0], inv1 = 1.f / lv[i][1];
        int row0 = q0 + rb + i * 16 + g;
        float* op0 = att_out + ((size_t)(b * TT + row0)) * DM + hh * 64;
        float* op1 = op0 + (size_t)8 * DM;
        #pragma unroll
        for (int dj = 0; dj < 8; dj++) {
            int c  = dj * 8 + 2 * tig;
            int p0 = perm8(c), p1 = perm8(c + 1);
            op0[p0] = rna(o[i][dj][0] * inv0);
            op0[p1] = rna(o[i][dj][1] * inv0);
            op1[p0] = rna(o[i][dj][2] * inv1);
            op1[p1] = rna(o[i][dj][3] * inv1);
        }
    }
}

// ---------------------------------------------------------------------------
// kernel_launch
// Inputs: 0:x  1:mask(unused)  2:freqs_cos  3:freqs_sin
//         4:qkv_w  5:qkv_b  6:proj_w  7:proj_b
// ---------------------------------------------------------------------------
extern "C" void kernel_launch(void* const* d_in, const int* in_sizes, int n_in,
                              void* d_out, int out_size) {
    const float* x      = (const float*)d_in[0];
    const float* fcos   = (const float*)d_in[2];
    const float* fsin   = (const float*)d_in[3];
    const float* qkv_w  = (const float*)d_in[4];
    const float* qkv_b  = (const float*)d_in[5];
    const float* proj_w = (const float*)d_in[6];
    const float* proj_b = (const float*)d_in[7];
    float* out = (float*)d_out;

    float *qkv2, *vtp, *att, *xT, *wq, *wp;
    cudaGetSymbolAddress((void**)&qkv2, g_qkv2);
    cudaGetSymbolAddress((void**)&vtp,  g_vt);
    cudaGetSymbolAddress((void**)&att,  g_att);
    cudaGetSymbolAddress((void**)&xT,   g_xT);
    cudaGetSymbolAddress((void**)&wq,   g_wq);
    cudaGetSymbolAddress((void**)&wp,   g_wp);

    cudaFuncSetAttribute(gemm_tc, cudaFuncAttributeMaxDynamicSharedMemorySize,
                         GSMEM_TOTAL);
    cudaFuncSetAttribute(attn_tc, cudaFuncAttributeMaxDynamicSharedMemorySize,
                         ASMEM_TOTAL);

    const int M = BB * TT;   // 8192

    // 0) operand prep
    prep_plain<<<(M * DM / 8) / 256, 256>>>(x, xT, M * DM / 8);
    prep_plain<<<(3 * DM * DM / 8) / 256, 256>>>(qkv_w, wq, 3 * DM * DM / 8);
    prep_plain<<<(DM * DM / 8) / 256, 256>>>(proj_w, wp, DM * DM / 8);

    // 1) QKV GEMM with fused rope/prep epilogue -> qkv2
    {
        dim3 grid(3 * DM / 128, M / 128);
        gemm_tc<<<grid, 128, GSMEM_TOTAL>>>(xT, wq, qkv_b, qkv2, M, 3 * DM, DM,
                                            1, fcos, fsin);
    }
    // 2) V transpose -> vt
    {
        dim3 grid(TT / 128, BB * NH);
        transpose_v<<<grid, 256>>>(qkv2, vtp);
    }
    // 3) causal attention -> att (prepped)
    {
        dim3 grid(TT / 256, BB * NH);
        attn_tc<<<grid, 256, ASMEM_TOTAL>>>(qkv2, vtp, att);
    }
    // 4) output projection -> d_out
    {
        dim3 grid(DM / 128, M / 128);
        gemm_tc<<<grid, 128, GSMEM_TOTAL>>>(att, wp, proj_b, out, M, DM, DM,
                                            0, nullptr, nullptr);
    }
}

// round 7
// speedup vs baseline: 1.0286x; 1.0286x over previous
#include <cuda_runtime.h>
#include <math_constants.h>
#include <cstdint>

#define BB 4
#define TT 2048
#define DM 1024
#define NH 16
#define DH 64

// Scratch. "prepped" = tf32-rounded bits, k-pair interleaved within 8-groups.
__device__ float g_qkv2[(size_t)BB * TT * 3 * DM]; // q,k prepped(+rope); v raw
__device__ float g_vt  [(size_t)BB * TT * DM];     // V^T per (b,h): [bh][d][t], prepped
__device__ float g_att [(size_t)BB * TT * DM];     // attention out, prepped for proj
__device__ float g_xT  [(size_t)BB * TT * DM];     // prepped x
__device__ float g_wq  [(size_t)3 * DM * DM];      // prepped qkv_w
__device__ float g_wp  [(size_t)DM * DM];          // prepped proj_w

// ===========================================================================
// Helpers
// ===========================================================================
__device__ __forceinline__ uint32_t f2tf32(float f) {
    uint32_t u;
    asm("cvt.rna.tf32.f32 %0, %1;" : "=r"(u) : "f"(f));
    return u;
}
__device__ __forceinline__ float rna(float f) { return __uint_as_float(f2tf32(f)); }

__device__ __forceinline__ void mma8(float* c, const uint32_t* a,
                                     uint32_t b0, uint32_t b1) {
    asm volatile(
        "mma.sync.aligned.m16n8k8.row.col.f32.tf32.tf32.f32 "
        "{%0,%1,%2,%3}, {%4,%5,%6,%7}, {%8,%9}, {%0,%1,%2,%3};"
        : "+f"(c[0]), "+f"(c[1]), "+f"(c[2]), "+f"(c[3])
        : "r"(a[0]), "r"(a[1]), "r"(a[2]), "r"(a[3]), "r"(b0), "r"(b1));
}

__device__ __forceinline__ uint32_t smem_u32(const void* p) {
    uint32_t a;
    asm("{ .reg .u64 t; cvta.to.shared.u64 t, %1; cvt.u32.u64 %0, t; }"
        : "=r"(a) : "l"(p));
    return a;
}
__device__ __forceinline__ void cpa16(uint32_t s, const void* g) {
    asm volatile("cp.async.ca.shared.global [%0], [%1], 16;" :: "r"(s), "l"(g));
}
#define CPA_COMMIT() asm volatile("cp.async.commit_group;" ::: "memory")
#define CPA_WAIT(n)  asm volatile("cp.async.wait_group %0;" :: "n"(n) : "memory")

// interleave permutation within 8-k groups: pairs (k, k+4) become adjacent
__device__ __forceinline__ int perm8(int k) {
    return (k & ~7) | (2 * (k & 3)) | ((k >> 2) & 1);
}

// XOR swizzle (8B-word granularity): word w of row r -> w ^ (4*(r&3))
__device__ __forceinline__ int swz(int r, int w) { return w ^ (4 * (r & 3)); }

// ===========================================================================
// prep_plain: tf32-round + k-pair interleave, 8 consecutive elements/thread
// ===========================================================================
__global__ void prep_plain(const float* __restrict__ src, float* __restrict__ dst,
                           int n8) {
    int i = blockIdx.x * blockDim.x + threadIdx.x;
    if (i >= n8) return;
    const float4* s = (const float4*)src + (size_t)i * 2;
    float4 v0 = s[0], v1 = s[1];
    float4 o0, o1;
    o0.x = rna(v0.x); o0.y = rna(v1.x); o0.z = rna(v0.y); o0.w = rna(v1.y);
    o1.x = rna(v0.z); o1.y = rna(v1.z); o1.z = rna(v0.w); o1.w = rna(v1.w);
    float4* d = (float4*)dst + (size_t)i * 2;
    d[0] = o0; d[1] = o1;
}

// ===========================================================================
// transpose_v: per (b,h), V [t][d] -> V^T [d][t], rna + key-interleave along t.
// ===========================================================================
__global__ void transpose_v(const float* __restrict__ qkv2, float* __restrict__ vt) {
    __shared__ float ts[128 * 69];
    const int tid = threadIdx.x;
    const int bh  = blockIdx.y;
    const int b   = bh >> 4;
    const int hh  = bh & 15;
    const int t0  = blockIdx.x * 128;

    const float* src = qkv2 + (size_t)b * TT * (3 * DM) + 2 * DM + hh * 64;
    #pragma unroll
    for (int it = 0; it < 8; it++) {
        int lin = tid + it * 256;
        int r = lin >> 4, c4 = lin & 15;
        float4 v = *(const float4*)(src + (size_t)(t0 + r) * (3 * DM) + c4 * 4);
        ts[r * 69 + c4 * 4 + 0] = v.x;
        ts[r * 69 + c4 * 4 + 1] = v.y;
        ts[r * 69 + c4 * 4 + 2] = v.z;
        ts[r * 69 + c4 * 4 + 3] = v.w;
    }
    __syncthreads();

    float* dst = vt + (size_t)bh * 64 * TT + t0;
    #pragma unroll
    for (int it = 0; it < 32; it++) {
        int lin = tid + it * 256;
        int d = lin >> 7, c = lin & 127;
        int tl = (c & ~7) | ((c & 1) << 2) | ((c >> 1) & 3);  // inverse interleave
        dst[(size_t)d * TT + c] = rna(ts[tl * 69 + d]);
    }
}

// ===========================================================================
// GEMM: C = A @ W^T + bias. A,W prepped. CTA 128x128, 4 warps, warp 64x64.
// 3-stage cp.async pipeline, exact 128B rows + XOR swizzle (conflict-free).
// mode 0: plain fp32 out. mode 1: fused qkv prep epilogue.
// ===========================================================================
#define GTILE (128 * 32)                   // floats per operand tile (16KB)
#define GSMEM_TOTAL (3 * 2 * GTILE * 4)    // 98304 B

__global__ void __launch_bounds__(128, 2)
gemm_tc(const float* __restrict__ A, const float* __restrict__ W,
        const float* __restrict__ bias, float* __restrict__ C,
        int M, int N, int K, int mode,
        const float* __restrict__ fcos, const float* __restrict__ fsin) {
    extern __shared__ float gsm[];
    const int tid  = threadIdx.x;
    const int wid  = tid >> 5;
    const int lane = tid & 31;
    const int g    = lane >> 2;
    const int tig  = lane & 3;
    const int wm   = wid & 1;
    const int wn   = wid >> 1;

    const int m0 = blockIdx.y * 128;
    const int n0 = blockIdx.x * 128;
    const uint32_t sbase = smem_u32(gsm);

    float acc[4][8][4];
    #pragma unroll
    for (int i = 0; i < 4; i++)
        #pragma unroll
        for (int j = 0; j < 8; j++)
            #pragma unroll
            for (int e = 0; e < 4; e++) acc[i][j][e] = 0.f;

    const int NK = K >> 5;

    auto load_stage = [&](int st, int k0) {
        #pragma unroll
        for (int it = 0; it < 16; it++) {
            int lin   = tid + it * 128;      // 0..2047
            int which = lin >> 10;           // 0=A, 1=B
            int r     = (lin & 1023) >> 3;   // 0..127
            int c4    = lin & 7;             // 16B chunk
            const float* src = which
                ? W + (size_t)(n0 + r) * K + k0 + c4 * 4
                : A + (size_t)(m0 + r) * K + k0 + c4 * 4;
            int pw = swz(r, 2 * c4);
            cpa16(sbase + (uint32_t)((st * 2 + which) * GTILE + r * 32 + pw * 2) * 4,
                  src);
        }
    };

    load_stage(0, 0);
    CPA_COMMIT();
    load_stage(1, 32);
    CPA_COMMIT();

    int cur = 0, pre = 2;
    for (int kt = 0; kt < NK; kt++) {
        if (kt + 1 < NK) CPA_WAIT(1); else CPA_WAIT(0);
        __syncthreads();   // all warps done with stage kt-1's buffer; stage kt landed

        if (kt + 2 < NK) {
            load_stage(pre, (kt + 2) << 5);
            CPA_COMMIT();
        }

        const float* sA = gsm + cur * 2 * GTILE;
        const float* sB = sA + GTILE;

        #pragma unroll
        for (int s = 0; s < 4; s++) {
            const int pw = (4 * s + tig) ^ (4 * (g & 3));
            uint32_t a[4][4];
            #pragma unroll
            for (int i = 0; i < 4; i++) {
                int r = wm * 64 + i * 16 + g;
                uint2 lo = *(const uint2*)&sA[r * 32 + pw * 2];
                uint2 hi = *(const uint2*)&sA[(r + 8) * 32 + pw * 2];
                a[i][0] = lo.x; a[i][1] = hi.x; a[i][2] = lo.y; a[i][3] = hi.y;
            }
            #pragma unroll
            for (int j = 0; j < 8; j++) {
                int n = wn * 64 + j * 8 + g;
                uint2 b = *(const uint2*)&sB[n * 32 + pw * 2];
                #pragma unroll
                for (int i = 0; i < 4; i++) mma8(acc[i][j], a[i], b.x, b.y);
            }
        }

        cur = (cur == 2) ? 0 : cur + 1;
        pre = (pre == 2) ? 0 : pre + 1;
    }

    #pragma unroll
    for (int i = 0; i < 4; i++) {
        int row0 = m0 + wm * 64 + i * 16 + g;
        int row1 = row0 + 8;
        #pragma unroll
        for (int j = 0; j < 8; j++) {
            int col = n0 + wn * 64 + j * 8 + 2 * tig;
            float bv0 = bias[col], bv1 = bias[col + 1];
            float v00 = acc[i][j][0] + bv0, v01 = acc[i][j][1] + bv1;
            float v10 = acc[i][j][2] + bv0, v11 = acc[i][j][3] + bv1;
            if (mode == 0) {
                *(float2*)(C + (size_t)row0 * N + col) = make_float2(v00, v01);
                *(float2*)(C + (size_t)row1 * N + col) = make_float2(v10, v11);
            } else {
                int sec = col >> 10;           // 0 q, 1 k, 2 v
                int d   = col & 63;
                if (sec < 2) {
                    float sc = (sec == 0) ? 0.125f : 1.f;
                    int t0i = row0 & (TT - 1), t1i = row1 & (TT - 1);
                    float c0 = fcos[t0i * 32 + (d >> 1)], s0 = fsin[t0i * 32 + (d >> 1)];
                    float c1 = fcos[t1i * 32 + (d >> 1)], s1 = fsin[t1i * 32 + (d >> 1)];
                    float r00 = (v00 * c0 - v01 * s0) * sc;
                    float r01 = (v00 * s0 + v01 * c0) * sc;
                    float r10 = (v10 * c1 - v11 * s1) * sc;
                    float r11 = (v10 * s1 + v11 * c1) * sc;
                    int cb = col & ~63;
                    int p0 = cb + perm8(d), p1 = cb + perm8(d + 1);
                    C[(size_t)row0 * N + p0] = rna(r00);
                    C[(size_t)row0 * N + p1] = rna(r01);
                    C[(size_t)row1 * N + p0] = rna(r10);
                    C[(size_t)row1 * N + p1] = rna(r11);
                } else {
                    *(float2*)(C + (size_t)row0 * N + col) = make_float2(v00, v01);
                    *(float2*)(C + (size_t)row1 * N + col) = make_float2(v10, v11);
                }
            }
        }
    }
}

// ===========================================================================
// Flash attention v7: 256-q blocks, 8 warps x 32 q-rows, P via shuffles,
// V consumed transposed. Exact 256B rows + XOR swizzle (conflict-free).
// ===========================================================================
#define QS_F (256 * 64)
#define KV_F (64 * 64)
#define ASMEM_TOTAL ((QS_F + 4 * KV_F) * 4)   // 131072 B

__global__ void __launch_bounds__(256, 1)
attn_tc(const float* __restrict__ qkv2, const float* __restrict__ vt,
        float* __restrict__ att_out) {
    extern __shared__ float asmf[];
    float* QS = asmf;
    float* KT = asmf + QS_F;
    float* VT = asmf + QS_F + 2 * KV_F;
    const uint32_t sbase = smem_u32(asmf);

    const int tid  = threadIdx.x;
    const int w    = tid >> 5;
    const int lane = tid & 31;
    const int g    = lane >> 2;
    const int tig  = lane & 3;
    const int rb   = w * 32;

    const int b   = blockIdx.y >> 4;
    const int hh  = blockIdx.y & 15;
    const int bxx = gridDim.x - 1 - blockIdx.x; // longest blocks first
    const int q0  = bxx * 256;

    const float* qb = qkv2 + (size_t)b * TT * (3 * DM) + hh * 64;
    const float* kb = qb + DM;
    const float* vb = vt + (size_t)blockIdx.y * 64 * TT;

    // --- stage Q: 256 rows x 16 chunks ---
    #pragma unroll
    for (int it = 0; it < 16; it++) {
        int lin = tid + it * 256;               // 0..4095
        int r = lin >> 4, c4 = lin & 15;
        int pw = swz(r, 2 * c4);
        cpa16(sbase + (uint32_t)(r * 64 + pw * 2) * 4,
              qb + (size_t)(q0 + r) * (3 * DM) + c4 * 4);
    }
    CPA_COMMIT();

    auto stage_kv = [&](int buf, int j0) {
        #pragma unroll
        for (int it = 0; it < 8; it++) {
            int lin   = tid + it * 256;         // 0..2047
            int which = lin >> 10;              // 0 K, 1 V
            int r  = (lin & 1023) >> 4;         // 0..63
            int c4 = lin & 15;
            const float* src = which
                ? vb + (size_t)r * TT + j0 + c4 * 4
                : kb + (size_t)(j0 + r) * (3 * DM) + c4 * 4;
            int pw = swz(r, 2 * c4);
            cpa16(sbase + (uint32_t)(QS_F + (which * 2 + buf) * KV_F
                                     + r * 64 + pw * 2) * 4, src);
        }
    };

    stage_kv(0, 0);
    CPA_COMMIT();
    CPA_WAIT(1);          // Q done
    __syncthreads();

    // --- Q fragments ---
    uint32_t qa[2][8][4];
    #pragma unroll
    for (int i = 0; i < 2; i++)
        #pragma unroll
        for (int s = 0; s < 8; s++) {
            int r  = rb + i * 16 + g;
            int pw = (4 * s + tig) ^ (4 * (g & 3));
            uint2 lo = *(const uint2*)&QS[r * 64 + pw * 2];
            uint2 hi = *(const uint2*)&QS[(r + 8) * 64 + pw * 2];
            qa[i][s][0] = lo.x; qa[i][s][1] = hi.x;
            qa[i][s][2] = lo.y; qa[i][s][3] = hi.y;
        }

    float o[2][8][4];
    #pragma unroll
    for (int i = 0; i < 2; i++)
        #pragma unroll
        for (int j = 0; j < 8; j++)
            #pragma unroll
            for (int e = 0; e < 4; e++) o[i][j][e] = 0.f;
    float mv[2][2] = {{-CUDART_INF_F, -CUDART_INF_F}, {-CUDART_INF_F, -CUDART_INF_F}};
    float lv[2][2] = {{0.f, 0.f}, {0.f, 0.f}};

    const int ntiles = 4 * (bxx + 1);
    const int srcA = 4 * g + (tig >> 1);
    const int srcB = srcA + 2;
    const bool odd = tig & 1;

    for (int tile = 0; tile < ntiles; tile++) {
        const int j0  = tile * 64;
        const int cur = tile & 1;

        if (tile + 1 < ntiles) {
            stage_kv(cur ^ 1, j0 + 64);
            CPA_COMMIT();
            CPA_WAIT(1);
        } else {
            CPA_WAIT(0);
        }
        __syncthreads();

        const float* Kc = KT + cur * KV_F;
        const float* Vc = VT + cur * KV_F;
        const bool active = (j0 <= q0 + rb + 31);

        if (active) {
            // --- S = Q @ K^T ---
            float p[2][8][4];
            #pragma unroll
            for (int i = 0; i < 2; i++)
                #pragma unroll
                for (int j = 0; j < 8; j++)
                    #pragma unroll
                    for (int e = 0; e < 4; e++) p[i][j][e] = 0.f;
            #pragma unroll
            for (int s = 0; s < 8; s++) {
                const int pw = (4 * s + tig) ^ (4 * (g & 3));
                #pragma unroll
                for (int j = 0; j < 8; j++) {
                    uint2 bb = *(const uint2*)&Kc[(j * 8 + g) * 64 + pw * 2];
                    mma8(p[0][j], qa[0][s], bb.x, bb.y);
                    mma8(p[1][j], qa[1][s], bb.x, bb.y);
                }
            }

            // --- causal mask on diagonal tiles ---
            if (j0 + 63 > q0 + rb) {
                #pragma unroll
                for (int i = 0; i < 2; i++) {
                    int row0 = q0 + rb + i * 16 + g;
                    int row1 = row0 + 8;
                    #pragma unroll
                    for (int j = 0; j < 8; j++) {
                        int col = j0 + j * 8 + 2 * tig;
                        if (col > row0)     p[i][j][0] = -CUDART_INF_F;
                        if (col + 1 > row0) p[i][j][1] = -CUDART_INF_F;
                        if (col > row1)     p[i][j][2] = -CUDART_INF_F;
                        if (col + 1 > row1) p[i][j][3] = -CUDART_INF_F;
                    }
                }
            }

            // --- online softmax ---
            #pragma unroll
            for (int i = 0; i < 2; i++) {
                float r0 = -CUDART_INF_F, r1 = -CUDART_INF_F;
                #pragma unroll
                for (int j = 0; j < 8; j++) {
                    r0 = fmaxf(r0, fmaxf(p[i][j][0], p[i][j][1]));
                    r1 = fmaxf(r1, fmaxf(p[i][j][2], p[i][j][3]));
                }
                r0 = fmaxf(r0, __shfl_xor_sync(0xffffffffu, r0, 1));
                r0 = fmaxf(r0, __shfl_xor_sync(0xffffffffu, r0, 2));
                r1 = fmaxf(r1, __shfl_xor_sync(0xffffffffu, r1, 1));
                r1 = fmaxf(r1, __shfl_xor_sync(0xffffffffu, r1, 2));
                float nm0 = fmaxf(mv[i][0], r0);
                float nm1 = fmaxf(mv[i][1], r1);
                float sc0 = __expf(mv[i][0] - nm0);
                float sc1 = __expf(mv[i][1] - nm1);
                float ls0 = 0.f, ls1 = 0.f;
                #pragma unroll
                for (int j = 0; j < 8; j++) {
                    p[i][j][0] = __expf(p[i][j][0] - nm0);
                    p[i][j][1] = __expf(p[i][j][1] - nm0);
                    p[i][j][2] = __expf(p[i][j][2] - nm1);
                    p[i][j][3] = __expf(p[i][j][3] - nm1);
                    ls0 += p[i][j][0] + p[i][j][1];
                    ls1 += p[i][j][2] + p[i][j][3];
                }
                ls0 += __shfl_xor_sync(0xffffffffu, ls0, 1);
                ls0 += __shfl_xor_sync(0xffffffffu, ls0, 2);
                ls1 += __shfl_xor_sync(0xffffffffu, ls1, 1);
                ls1 += __shfl_xor_sync(0xffffffffu, ls1, 2);
                mv[i][0] = nm0; mv[i][1] = nm1;
                lv[i][0] = lv[i][0] * sc0 + ls0;
                lv[i][1] = lv[i][1] * sc1 + ls1;
                #pragma unroll
                for (int j = 0; j < 8; j++) {
                    o[i][j][0] *= sc0; o[i][j][1] *= sc0;
                    o[i][j][2] *= sc1; o[i][j][3] *= sc1;
                }
            }

            // --- O += P @ V : P -> A-frag layout via shuffles ---
            #pragma unroll
            for (int s = 0; s < 8; s++) {
                uint32_t pa[2][4];
                #pragma unroll
                for (int i = 0; i < 2; i++) {
                    float x0 = __shfl_sync(0xffffffffu, p[i][s][0], srcA);
                    float x1 = __shfl_sync(0xffffffffu, p[i][s][1], srcA);
                    float x2 = __shfl_sync(0xffffffffu, p[i][s][2], srcA);
                    float x3 = __shfl_sync(0xffffffffu, p[i][s][3], srcA);
                    float y0 = __shfl_sync(0xffffffffu, p[i][s][0], srcB);
                    float y1 = __shfl_sync(0xffffffffu, p[i][s][1], srcB);
                    float y2 = __shfl_sync(0xffffffffu, p[i][s][2], srcB);
                    float y3 = __shfl_sync(0xffffffffu, p[i][s][3], srcB);
                    pa[i][0] = __float_as_uint(odd ? x1 : x0);
                    pa[i][1] = __float_as_uint(odd ? x3 : x2);
                    pa[i][2] = __float_as_uint(odd ? y1 : y0);
                    pa[i][3] = __float_as_uint(odd ? y3 : y2);
                }
                const int pw = (4 * s + tig) ^ (4 * (g & 3));
                #pragma unroll
                for (int dj = 0; dj < 8; dj++) {
                    uint2 vv = *(const uint2*)&Vc[(dj * 8 + g) * 64 + pw * 2];
                    mma8(o[0][dj], pa[0], vv.x, vv.y);
                    mma8(o[1][dj], pa[1], vv.x, vv.y);
                }
            }
        }
        __syncthreads();
    }

    // --- normalize + store prepped (rna + perm8) for proj GEMM ---
    #pragma unroll
    for (int i = 0; i < 2; i++) {
        float inv0 = 1.f / lv[i][0], inv1 = 1.f / lv[i][1];
        int row0 = q0 + rb + i * 16 + g;
        float* op0 = att_out + ((size_t)(b * TT + row0)) * DM + hh * 64;
        float* op1 = op0 + (size_t)8 * DM;
        #pragma unroll
        for (int dj = 0; dj < 8; dj++) {
            int c  = dj * 8 + 2 * tig;
            int p0 = perm8(c), p1 = perm8(c + 1);
            op0[p0] = rna(o[i][dj][0] * inv0);
            op0[p1] = rna(o[i][dj][1] * inv0);
            op1[p0] = rna(o[i][dj][2] * inv1);
            op1[p1] = rna(o[i][dj][3] * inv1);
        }
    }
}

// ---------------------------------------------------------------------------
// kernel_launch
// Inputs: 0:x  1:mask(unused)  2:freqs_cos  3:freqs_sin
//         4:qkv_w  5:qkv_b  6:proj_w  7:proj_b
// ---------------------------------------------------------------------------
extern "C" void kernel_launch(void* const* d_in, const int* in_sizes, int n_in,
                              void* d_out, int out_size) {
    const float* x      = (const float*)d_in[0];
    const float* fcos   = (const float*)d_in[2];
    const float* fsin   = (const float*)d_in[3];
    const float* qkv_w  = (const float*)d_in[4];
    const float* qkv_b  = (const float*)d_in[5];
    const float* proj_w = (const float*)d_in[6];
    const float* proj_b = (const float*)d_in[7];
    float* out = (float*)d_out;

    float *qkv2, *vtp, *att, *xT, *wq, *wp;
    cudaGetSymbolAddress((void**)&qkv2, g_qkv2);
    cudaGetSymbolAddress((void**)&vtp,  g_vt);
    cudaGetSymbolAddress((void**)&att,  g_att);
    cudaGetSymbolAddress((void**)&xT,   g_xT);
    cudaGetSymbolAddress((void**)&wq,   g_wq);
    cudaGetSymbolAddress((void**)&wp,   g_wp);

    cudaFuncSetAttribute(gemm_tc, cudaFuncAttributeMaxDynamicSharedMemorySize,
                         GSMEM_TOTAL);
    cudaFuncSetAttribute(attn_tc, cudaFuncAttributeMaxDynamicSharedMemorySize,
                         ASMEM_TOTAL);

    const int M = BB * TT;   // 8192

    // 0) operand prep
    prep_plain<<<(M * DM / 8) / 256, 256>>>(x, xT, M * DM / 8);
    prep_plain<<<(3 * DM * DM / 8) / 256, 256>>>(qkv_w, wq, 3 * DM * DM / 8);
    prep_plain<<<(DM * DM / 8) / 256, 256>>>(proj_w, wp, DM * DM / 8);

    // 1) QKV GEMM with fused rope/prep epilogue -> qkv2
    {
        dim3 grid(3 * DM / 128, M / 128);
        gemm_tc<<<grid, 128, GSMEM_TOTAL>>>(xT, wq, qkv_b, qkv2, M, 3 * DM, DM,
                                            1, fcos, fsin);
    }
    // 2) V transpose -> vt
    {
        dim3 grid(TT / 128, BB * NH);
        transpose_v<<<grid, 256>>>(qkv2, vtp);
    }
    // 3) causal attention -> att (prepped)
    {
        dim3 grid(TT / 256, BB * NH);
        attn_tc<<<grid, 256, ASMEM_TOTAL>>>(qkv2, vtp, att);
    }
    // 4) output projection -> d_out
    {
        dim3 grid(DM / 128, M / 128);
        gemm_tc<<<grid, 128, GSMEM_TOTAL>>>(att, wp, proj_b, out, M, DM, DM,
                                            0, nullptr, nullptr);
    }
}

// round 8
// speedup vs baseline: 1.8820x; 1.8297x over previous
#include <cuda_runtime.h>
#include <cuda_fp16.h>
#include <math_constants.h>
#include <cstdint>

#define BB 4
#define TT 2048
#define DM 1024
#define NH 16
#define DH 64

// Scratch (fp16). "prepped" = fp16 + 4B-word interleave within 8-word k-groups.
__device__ __half g_qkv2[(size_t)BB * TT * 3 * DM]; // q,k prepped(+rope); v plain fp16
__device__ __half g_vt  [(size_t)BB * TT * DM];     // V^T per (b,h): [bh][d][t], t-interleaved
__device__ __half g_att [(size_t)BB * TT * DM];     // attention out, prepped for proj
__device__ __half g_x16 [(size_t)BB * TT * DM];     // prepped x
__device__ __half g_wq  [(size_t)3 * DM * DM];      // prepped qkv_w
__device__ __half g_wp  [(size_t)DM * DM];          // prepped proj_w

// ===========================================================================
// Helpers
// ===========================================================================
__device__ __forceinline__ uint32_t packh2(float x, float y) {
    __half2 h = __floats2half2_rn(x, y);
    return *reinterpret_cast<uint32_t*>(&h);
}

// D += A(16x16,row) * B(16x8,col), fp16 inputs, fp32 accum
__device__ __forceinline__ void mma16(float* c, const uint32_t* a,
                                      uint32_t b0, uint32_t b1) {
    asm volatile(
        "mma.sync.aligned.m16n8k16.row.col.f32.f16.f16.f32 "
        "{%0,%1,%2,%3}, {%4,%5,%6,%7}, {%8,%9}, {%0,%1,%2,%3};"
        : "+f"(c[0]), "+f"(c[1]), "+f"(c[2]), "+f"(c[3])
        : "r"(a[0]), "r"(a[1]), "r"(a[2]), "r"(a[3]), "r"(b0), "r"(b1));
}

__device__ __forceinline__ uint32_t smem_u32(const void* p) {
    uint32_t a;
    asm("{ .reg .u64 t; cvta.to.shared.u64 t, %1; cvt.u32.u64 %0, t; }"
        : "=r"(a) : "l"(p));
    return a;
}
__device__ __forceinline__ void cpa16(uint32_t s, const void* g) {
    asm volatile("cp.async.ca.shared.global [%0], [%1], 16;" :: "r"(s), "l"(g));
}
#define CPA_COMMIT() asm volatile("cp.async.commit_group;" ::: "memory")
#define CPA_WAIT(n)  asm volatile("cp.async.wait_group %0;" :: "n"(n) : "memory")

// word-interleave within 8-word (16-half) groups: words (w, w+4) -> adjacent
__device__ __forceinline__ int permw(int w) {
    return (w & ~7) | ((w & 3) << 1) | ((w >> 2) & 1);
}

// ===========================================================================
// prep_plain: fp32 -> fp16, word-interleave. 16 elements per thread.
// ===========================================================================
__global__ void prep_plain(const float* __restrict__ src, __half* __restrict__ dst,
                           int n16) {
    int i = blockIdx.x * blockDim.x + threadIdx.x;
    if (i >= n16) return;
    const float4* s = (const float4*)src + (size_t)i * 4;
    float4 f0 = s[0], f1 = s[1], f2 = s[2], f3 = s[3];
    uint32_t w0 = packh2(f0.x, f0.y), w1 = packh2(f0.z, f0.w);
    uint32_t w2 = packh2(f1.x, f1.y), w3 = packh2(f1.z, f1.w);
    uint32_t w4 = packh2(f2.x, f2.y), w5 = packh2(f2.z, f2.w);
    uint32_t w6 = packh2(f3.x, f3.y), w7 = packh2(f3.z, f3.w);
    uint4* d = (uint4*)(dst + (size_t)i * 16);
    d[0] = make_uint4(w0, w4, w1, w5);
    d[1] = make_uint4(w2, w6, w3, w7);
}

// ===========================================================================
// transpose_v: per (b,h), V [t][d] fp16 -> V^T [d][t], interleaved along t.
// ===========================================================================
__global__ void transpose_v(const __half* __restrict__ qkv2, __half* __restrict__ vt) {
    __shared__ __half ts[128 * 72];
    const int tid = threadIdx.x;
    const int bh  = blockIdx.y;
    const int b   = bh >> 4;
    const int hh  = bh & 15;
    const int t0  = blockIdx.x * 128;

    const __half* src = qkv2 + (size_t)b * TT * (3 * DM) + 2 * DM + hh * 64;
    #pragma unroll
    for (int it = 0; it < 4; it++) {
        int lin = tid + it * 256;        // 0..1023 (128 rows x 8 chunks)
        int r = lin >> 3, c4 = lin & 7;
        uint4 v = *(const uint4*)(src + (size_t)(t0 + r) * (3 * DM) + c4 * 8);
        *(uint4*)&ts[r * 72 + c4 * 8] = v;
    }
    __syncthreads();

    __half* dst = vt + (size_t)bh * 64 * TT + t0;
    #pragma unroll
    for (int it = 0; it < 16; it++) {
        int lin = tid + it * 256;        // 0..4095 (64 d x 64 out-words)
        int d = lin >> 6, c = lin & 63;
        int sw = (c & ~7) | ((c & 1) << 2) | ((c >> 1) & 3);  // inverse interleave
        int t  = 2 * sw;
        __half2 h = __halves2half2(ts[t * 72 + d], ts[(t + 1) * 72 + d]);
        *(__half2*)(dst + (size_t)d * TT + 2 * c) = h;
    }
}

// ===========================================================================
// GEMM: C = A @ W^T + bias. A,W prepped fp16. CTA 128x128, 4 warps (2x2),
// warp tile 64x64, BK=64 halves (128B rows), 3-stage cp.async, XOR swizzle.
// mode 0: fp32 out. mode 1: fused qkv prep epilogue (fp16 out).
// ===========================================================================
#define GW 32                               // 4B words per row
#define GTILE (128 * GW)                    // words per operand tile (16KB)
#define GSMEM_TOTAL (3 * 2 * GTILE * 4)     // 98304 B

__global__ void __launch_bounds__(128, 2)
gemm_tc(const __half* __restrict__ A, const __half* __restrict__ W,
        const float* __restrict__ bias, void* __restrict__ Cv,
        int M, int N, int K, int mode,
        const float* __restrict__ fcos, const float* __restrict__ fsin) {
    extern __shared__ uint32_t gsm[];
    const int tid  = threadIdx.x;
    const int wid  = tid >> 5;
    const int lane = tid & 31;
    const int g    = lane >> 2;
    const int tig  = lane & 3;
    const int wm   = wid & 1;
    const int wn   = wid >> 1;

    const int m0 = blockIdx.y * 128;
    const int n0 = blockIdx.x * 128;
    const uint32_t sbase = smem_u32(gsm);

    float acc[4][8][4];
    #pragma unroll
    for (int i = 0; i < 4; i++)
        #pragma unroll
        for (int j = 0; j < 8; j++)
            #pragma unroll
            for (int e = 0; e < 4; e++) acc[i][j][e] = 0.f;

    const int NK = K >> 6;   // K/64

    auto load_stage = [&](int st, int k0) {
        #pragma unroll
        for (int it = 0; it < 16; it++) {
            int lin   = tid + it * 128;      // 0..2047
            int which = lin >> 10;           // 0=A, 1=B
            int r     = (lin & 1023) >> 3;   // 0..127
            int c4    = lin & 7;             // 16B chunk (8 halves)
            const __half* src = which
                ? W + (size_t)(n0 + r) * K + k0 + c4 * 8
                : A + (size_t)(m0 + r) * K + k0 + c4 * 8;
            int u8 = (2 * c4) ^ (4 * (r & 3));
            cpa16(sbase + (uint32_t)((st * 2 + which) * GTILE + r * GW + u8 * 2) * 4,
                  src);
        }
    };

    load_stage(0, 0);
    CPA_COMMIT();
    load_stage(1, 64);
    CPA_COMMIT();

    int cur = 0, pre = 2;
    for (int kt = 0; kt < NK; kt++) {
        if (kt + 1 < NK) CPA_WAIT(1); else CPA_WAIT(0);
        __syncthreads();

        if (kt + 2 < NK) {
            load_stage(pre, (kt + 2) << 6);
            CPA_COMMIT();
        }

        const uint32_t* sA = gsm + cur * 2 * GTILE;
        const uint32_t* sB = sA + GTILE;

        #pragma unroll
        for (int s = 0; s < 4; s++) {
            const int pw = (4 * s + tig) ^ (4 * (g & 3));
            uint32_t a[4][4];
            #pragma unroll
            for (int i = 0; i < 4; i++) {
                int r = wm * 64 + i * 16 + g;
                uint2 lo = *(const uint2*)&sA[r * GW + pw * 2];
                uint2 hi = *(const uint2*)&sA[(r + 8) * GW + pw * 2];
                a[i][0] = lo.x; a[i][1] = hi.x; a[i][2] = lo.y; a[i][3] = hi.y;
            }
            #pragma unroll
            for (int j = 0; j < 8; j++) {
                int n = wn * 64 + j * 8 + g;
                uint2 b = *(const uint2*)&sB[n * GW + pw * 2];
                #pragma unroll
                for (int i = 0; i < 4; i++) mma16(acc[i][j], a[i], b.x, b.y);
            }
        }

        cur = (cur == 2) ? 0 : cur + 1;
        pre = (pre == 2) ? 0 : pre + 1;
    }

    #pragma unroll
    for (int i = 0; i < 4; i++) {
        int row0 = m0 + wm * 64 + i * 16 + g;
        int row1 = row0 + 8;
        #pragma unroll
        for (int j = 0; j < 8; j++) {
            int col = n0 + wn * 64 + j * 8 + 2 * tig;
            float bv0 = bias[col], bv1 = bias[col + 1];
            float v00 = acc[i][j][0] + bv0, v01 = acc[i][j][1] + bv1;
            float v10 = acc[i][j][2] + bv0, v11 = acc[i][j][3] + bv1;
            if (mode == 0) {
                float* C = (float*)Cv;
                *(float2*)(C + (size_t)row0 * N + col) = make_float2(v00, v01);
                *(float2*)(C + (size_t)row1 * N + col) = make_float2(v10, v11);
            } else {
                __half* C = (__half*)Cv;
                int sec = col >> 10;           // 0 q, 1 k, 2 v
                int d   = col & 63;
                if (sec < 2) {
                    float sc = (sec == 0) ? 0.125f : 1.f;
                    int t0i = row0 & (TT - 1), t1i = row1 & (TT - 1);
                    float c0 = fcos[t0i * 32 + (d >> 1)], s0 = fsin[t0i * 32 + (d >> 1)];
                    float c1 = fcos[t1i * 32 + (d >> 1)], s1 = fsin[t1i * 32 + (d >> 1)];
                    float r00 = (v00 * c0 - v01 * s0) * sc;
                    float r01 = (v00 * s0 + v01 * c0) * sc;
                    float r10 = (v10 * c1 - v11 * s1) * sc;
                    float r11 = (v10 * s1 + v11 * c1) * sc;
                    int cb = col & ~63;
                    int pw = permw(d >> 1);
                    *(__half2*)(C + (size_t)row0 * N + cb + 2 * pw) =
                        __floats2half2_rn(r00, r01);
                    *(__half2*)(C + (size_t)row1 * N + cb + 2 * pw) =
                        __floats2half2_rn(r10, r11);
                } else {
                    *(__half2*)(C + (size_t)row0 * N + col) = __floats2half2_rn(v00, v01);
                    *(__half2*)(C + (size_t)row1 * N + col) = __floats2half2_rn(v10, v11);
                }
            }
        }
    }
}

// ===========================================================================
// Flash attention v8 (fp16 mma): 256-q blocks, 8 warps x 32 q-rows.
// P maps directly onto fp16 A-fragments (no shuffles). V^T tiles as B-operand.
// ===========================================================================
#define QW (256 * 32)                      // Q tile words (32KB)
#define KVWW (64 * 32)                     // K or V tile words (8KB)
#define ASMEM_TOTAL ((QW + 4 * KVWW) * 4)  // 65536 B

__global__ void __launch_bounds__(256, 1)
attn_tc(const __half* __restrict__ qkv2, const __half* __restrict__ vt,
        __half* __restrict__ att_out) {
    extern __shared__ uint32_t asmw[];
    uint32_t* QS = asmw;
    uint32_t* KT = asmw + QW;
    uint32_t* VT = asmw + QW + 2 * KVWW;
    const uint32_t sbase = smem_u32(asmw);

    const int tid  = threadIdx.x;
    const int w    = tid >> 5;
    const int lane = tid & 31;
    const int g    = lane >> 2;
    const int tig  = lane & 3;
    const int rb   = w * 32;

    const int b   = blockIdx.y >> 4;
    const int hh  = blockIdx.y & 15;
    const int bxx = gridDim.x - 1 - blockIdx.x;   // longest blocks first
    const int q0  = bxx * 256;

    const __half* qb = qkv2 + (size_t)b * TT * (3 * DM) + hh * 64;
    const __half* kb = qb + DM;
    const __half* vb = vt + (size_t)blockIdx.y * 64 * TT;

    // --- stage Q: 256 rows x 8 chunks ---
    #pragma unroll
    for (int it = 0; it < 8; it++) {
        int lin = tid + it * 256;            // 0..2047
        int r = lin >> 3, c4 = lin & 7;
        int u8 = (2 * c4) ^ (4 * (r & 3));
        cpa16(sbase + (uint32_t)(r * 32 + u8 * 2) * 4,
              qb + (size_t)(q0 + r) * (3 * DM) + c4 * 8);
    }
    CPA_COMMIT();

    auto stage_kv = [&](int buf, int j0) {
        #pragma unroll
        for (int it = 0; it < 4; it++) {
            int lin   = tid + it * 256;      // 0..1023
            int which = lin >> 9;            // 0 K, 1 V
            int r  = (lin & 511) >> 3;       // 0..63
            int c4 = lin & 7;
            const __half* src = which
                ? vb + (size_t)r * TT + j0 + c4 * 8
                : kb + (size_t)(j0 + r) * (3 * DM) + c4 * 8;
            int u8 = (2 * c4) ^ (4 * (r & 3));
            cpa16(sbase + (uint32_t)(QW + (which * 2 + buf) * KVWW
                                     + r * 32 + u8 * 2) * 4, src);
        }
    };

    stage_kv(0, 0);
    CPA_COMMIT();
    CPA_WAIT(1);          // Q done
    __syncthreads();

    // --- Q fragments ---
    uint32_t qa[2][4][4];
    #pragma unroll
    for (int i = 0; i < 2; i++)
        #pragma unroll
        for (int s = 0; s < 4; s++) {
            int r  = rb + i * 16 + g;
            int pw = (4 * s + tig) ^ (4 * (g & 3));
            uint2 lo = *(const uint2*)&QS[r * 32 + pw * 2];
            uint2 hi = *(const uint2*)&QS[(r + 8) * 32 + pw * 2];
            qa[i][s][0] = lo.x; qa[i][s][1] = hi.x;
            qa[i][s][2] = lo.y; qa[i][s][3] = hi.y;
        }

    float o[2][8][4];
    #pragma unroll
    for (int i = 0; i < 2; i++)
        #pragma unroll
        for (int j = 0; j < 8; j++)
            #pragma unroll
            for (int e = 0; e < 4; e++) o[i][j][e] = 0.f;
    float mv[2][2] = {{-CUDART_INF_F, -CUDART_INF_F}, {-CUDART_INF_F, -CUDART_INF_F}};
    float lv[2][2] = {{0.f, 0.f}, {0.f, 0.f}};

    const int ntiles = 4 * (bxx + 1);

    for (int tile = 0; tile < ntiles; tile++) {
        const int j0  = tile * 64;
        const int cur = tile & 1;

        if (tile + 1 < ntiles) {
            stage_kv(cur ^ 1, j0 + 64);
            CPA_COMMIT();
            CPA_WAIT(1);
        } else {
            CPA_WAIT(0);
        }
        __syncthreads();

        const uint32_t* Kc = KT + cur * KVWW;
        const uint32_t* Vc = VT + cur * KVWW;
        const bool active = (j0 <= q0 + rb + 31);

        if (active) {
            // --- S = Q @ K^T ---
            float p[2][8][4];
            #pragma unroll
            for (int i = 0; i < 2; i++)
                #pragma unroll
                for (int j = 0; j < 8; j++)
                    #pragma unroll
                    for (int e = 0; e < 4; e++) p[i][j][e] = 0.f;
            #pragma unroll
            for (int s = 0; s < 4; s++) {
                const int pw = (4 * s + tig) ^ (4 * (g & 3));
                #pragma unroll
                for (int j = 0; j < 8; j++) {
                    uint2 bb = *(const uint2*)&Kc[(j * 8 + g) * 32 + pw * 2];
                    mma16(p[0][j], qa[0][s], bb.x, bb.y);
                    mma16(p[1][j], qa[1][s], bb.x, bb.y);
                }
            }

            // --- causal mask on diagonal tiles ---
            if (j0 + 63 > q0 + rb) {
                #pragma unroll
                for (int i = 0; i < 2; i++) {
                    int row0 = q0 + rb + i * 16 + g;
                    int row1 = row0 + 8;
                    #pragma unroll
                    for (int j = 0; j < 8; j++) {
                        int col = j0 + j * 8 + 2 * tig;
                        if (col > row0)     p[i][j][0] = -CUDART_INF_F;
                        if (col + 1 > row0) p[i][j][1] = -CUDART_INF_F;
                        if (col > row1)     p[i][j][2] = -CUDART_INF_F;
                        if (col + 1 > row1) p[i][j][3] = -CUDART_INF_F;
                    }
                }
            }

            // --- online softmax ---
            #pragma unroll
            for (int i = 0; i < 2; i++) {
                float r0 = -CUDART_INF_F, r1 = -CUDART_INF_F;
                #pragma unroll
                for (int j = 0; j < 8; j++) {
                    r0 = fmaxf(r0, fmaxf(p[i][j][0], p[i][j][1]));
                    r1 = fmaxf(r1, fmaxf(p[i][j][2], p[i][j][3]));
                }
                r0 = fmaxf(r0, __shfl_xor_sync(0xffffffffu, r0, 1));
                r0 = fmaxf(r0, __shfl_xor_sync(0xffffffffu, r0, 2));
                r1 = fmaxf(r1, __shfl_xor_sync(0xffffffffu, r1, 1));
                r1 = fmaxf(r1, __shfl_xor_sync(0xffffffffu, r1, 2));
                float nm0 = fmaxf(mv[i][0], r0);
                float nm1 = fmaxf(mv[i][1], r1);
                float sc0 = __expf(mv[i][0] - nm0);
                float sc1 = __expf(mv[i][1] - nm1);
                float ls0 = 0.f, ls1 = 0.f;
                #pragma unroll
                for (int j = 0; j < 8; j++) {
                    p[i][j][0] = __expf(p[i][j][0] - nm0);
                    p[i][j][1] = __expf(p[i][j][1] - nm0);
                    p[i][j][2] = __expf(p[i][j][2] - nm1);
                    p[i][j][3] = __expf(p[i][j][3] - nm1);
                    ls0 += p[i][j][0] + p[i][j][1];
                    ls1 += p[i][j][2] + p[i][j][3];
                }
                ls0 += __shfl_xor_sync(0xffffffffu, ls0, 1);
                ls0 += __shfl_xor_sync(0xffffffffu, ls0, 2);
                ls1 += __shfl_xor_sync(0xffffffffu, ls1, 1);
                ls1 += __shfl_xor_sync(0xffffffffu, ls1, 2);
                mv[i][0] = nm0; mv[i][1] = nm1;
                lv[i][0] = lv[i][0] * sc0 + ls0;
                lv[i][1] = lv[i][1] * sc1 + ls1;
                #pragma unroll
                for (int j = 0; j < 8; j++) {
                    o[i][j][0] *= sc0; o[i][j][1] *= sc0;
                    o[i][j][2] *= sc1; o[i][j][3] *= sc1;
                }
            }

            // --- O += P @ V : S-frag == fp16 A-frag layout, just pack ---
            #pragma unroll
            for (int s = 0; s < 4; s++) {
                uint32_t pa[2][4];
                #pragma unroll
                for (int i = 0; i < 2; i++) {
                    pa[i][0] = packh2(p[i][2 * s][0],     p[i][2 * s][1]);
                    pa[i][1] = packh2(p[i][2 * s][2],     p[i][2 * s][3]);
                    pa[i][2] = packh2(p[i][2 * s + 1][0], p[i][2 * s + 1][1]);
                    pa[i][3] = packh2(p[i][2 * s + 1][2], p[i][2 * s + 1][3]);
                }
                const int pw = (4 * s + tig) ^ (4 * (g & 3));
                #pragma unroll
                for (int dj = 0; dj < 8; dj++) {
                    uint2 vv = *(const uint2*)&Vc[(dj * 8 + g) * 32 + pw * 2];
                    mma16(o[0][dj], pa[0], vv.x, vv.y);
                    mma16(o[1][dj], pa[1], vv.x, vv.y);
                }
            }
        }
        __syncthreads();
    }

    // --- normalize + store prepped fp16 (interleaved) for proj GEMM ---
    #pragma unroll
    for (int i = 0; i < 2; i++) {
        float inv0 = 1.f / lv[i][0], inv1 = 1.f / lv[i][1];
        int row0 = q0 + rb + i * 16 + g;
        __half* op0 = att_out + ((size_t)(b * TT + row0)) * DM + hh * 64;
        __half* op1 = op0 + (size_t)8 * DM;
        #pragma unroll
        for (int dj = 0; dj < 8; dj++) {
            int pw = permw(dj * 4 + tig);
            *(__half2*)(op0 + 2 * pw) = __floats2half2_rn(o[i][dj][0] * inv0,
                                                          o[i][dj][1] * inv0);
            *(__half2*)(op1 + 2 * pw) = __floats2half2_rn(o[i][dj][2] * inv1,
                                                          o[i][dj][3] * inv1);
        }
    }
}

// ---------------------------------------------------------------------------
// kernel_launch
// Inputs: 0:x  1:mask(unused)  2:freqs_cos  3:freqs_sin
//         4:qkv_w  5:qkv_b  6:proj_w  7:proj_b
// ---------------------------------------------------------------------------
extern "C" void kernel_launch(void* const* d_in, const int* in_sizes, int n_in,
                              void* d_out, int out_size) {
    const float* x      = (const float*)d_in[0];
    const float* fcos   = (const float*)d_in[2];
    const float* fsin   = (const float*)d_in[3];
    const float* qkv_w  = (const float*)d_in[4];
    const float* qkv_b  = (const float*)d_in[5];
    const float* proj_w = (const float*)d_in[6];
    const float* proj_b = (const float*)d_in[7];
    float* out = (float*)d_out;

    __half *qkv2, *vtp, *att, *x16, *wq, *wp;
    cudaGetSymbolAddress((void**)&qkv2, g_qkv2);
    cudaGetSymbolAddress((void**)&vtp,  g_vt);
    cudaGetSymbolAddress((void**)&att,  g_att);
    cudaGetSymbolAddress((void**)&x16,  g_x16);
    cudaGetSymbolAddress((void**)&wq,   g_wq);
    cudaGetSymbolAddress((void**)&wp,   g_wp);

    cudaFuncSetAttribute(gemm_tc, cudaFuncAttributeMaxDynamicSharedMemorySize,
                         GSMEM_TOTAL);
    cudaFuncSetAttribute(attn_tc, cudaFuncAttributeMaxDynamicSharedMemorySize,
                         ASMEM_TOTAL);

    const int M = BB * TT;   // 8192

    // 0) operand prep: fp32 -> fp16 + interleave
    prep_plain<<<(M * DM / 16) / 256, 256>>>(x, x16, M * DM / 16);
    prep_plain<<<(3 * DM * DM / 16) / 256, 256>>>(qkv_w, wq, 3 * DM * DM / 16);
    prep_plain<<<(DM * DM / 16) / 256, 256>>>(proj_w, wp, DM * DM / 16);

    // 1) QKV GEMM with fused rope/prep epilogue -> qkv2 (fp16)
    {
        dim3 grid(3 * DM / 128, M / 128);
        gemm_tc<<<grid, 128, GSMEM_TOTAL>>>(x16, wq, qkv_b, qkv2, M, 3 * DM, DM,
                                            1, fcos, fsin);
    }
    // 2) V transpose -> vt
    {
        dim3 grid(TT / 128, BB * NH);
        transpose_v<<<grid, 256>>>(qkv2, vtp);
    }
    // 3) causal attention -> att (prepped fp16)
    {
        dim3 grid(TT / 256, BB * NH);
        attn_tc<<<grid, 256, ASMEM_TOTAL>>>(qkv2, vtp, att);
    }
    // 4) output projection -> d_out (fp32)
    {
        dim3 grid(DM / 128, M / 128);
        gemm_tc<<<grid, 128, GSMEM_TOTAL>>>(att, wp, proj_b, out, M, DM, DM,
                                            0, nullptr, nullptr);
    }
}